// round 16
// baseline (speedup 1.0000x reference)
#include <cuda_runtime.h>
#include <math.h>
#include <stdint.h>

#define Dd  512
#define Hh  8
#define HD  64
#define Bb  2
#define Ss  256
#define Ff  2048
#define Cc  4
#define Vv  32000
#define TOK (Bb*Ss)   // 512

// ---------------- device state (no allocation allowed) ----------------
__device__ float g_x  [TOK*Dd];
__device__ float g_xnh[TOK*Dd];
__device__ float g_xnl[TOK*Dd];
__device__ float g_q  [TOK*Dd];
__device__ float g_k  [TOK*Dd];
__device__ float g_v  [TOK*Dd];
__device__ float g_oh [TOK*Dd];
__device__ float g_ol [TOK*Dd];
__device__ float g_ffh[TOK*Ff];
__device__ float g_ffl[TOK*Ff];
__device__ float g_part[6*TOK*Dd];
__device__ float g_att[Bb*Hh*8*4*32*64];   // attention O partials (4 MB)
__device__ float g_ml [Bb*Hh*8*4*32*2];    // per-row (m, l) partials
__device__ float g_pool[Bb*Dd];
__device__ int   g_cur[Bb];
__device__ float g_accp[Cc+1];
__device__ float g_acclb;

// ---------------- tf32 / cp.async helpers ----------------
__device__ __forceinline__ uint32_t f2tf32(float f) {
    uint32_t u;
    asm volatile("cvt.rna.tf32.f32 %0, %1;" : "=r"(u) : "f"(f));
    return u;
}

__device__ __forceinline__ void split_store(float v, float* __restrict__ ph, float* __restrict__ pl) {
    uint32_t h = f2tf32(v);
    *ph = __uint_as_float(h);
    uint32_t l = f2tf32(v - __uint_as_float(h));
    *pl = __uint_as_float(l);
}

__device__ __forceinline__ void mma_tf32(float c[4],
    uint32_t a0, uint32_t a1, uint32_t a2, uint32_t a3,
    uint32_t b0, uint32_t b1)
{
    asm volatile(
        "mma.sync.aligned.m16n8k8.row.col.f32.tf32.tf32.f32 "
        "{%0,%1,%2,%3}, {%4,%5,%6,%7}, {%8,%9}, {%0,%1,%2,%3};"
        : "+f"(c[0]), "+f"(c[1]), "+f"(c[2]), "+f"(c[3])
        : "r"(a0), "r"(a1), "r"(a2), "r"(a3), "r"(b0), "r"(b1));
}

__device__ __forceinline__ void cp_async16(float* smem, const float* gmem) {
    uint32_t s;
    asm("{ .reg .u64 t; cvta.to.shared.u64 t, %1; cvt.u32.u64 %0, t; }"
        : "=r"(s) : "l"(smem));
    asm volatile("cp.async.cg.shared.global [%0], [%1], 16;" :: "r"(s), "l"(gmem) : "memory");
}
#define CP_COMMIT()  asm volatile("cp.async.commit_group;" ::: "memory")
#define CP_WAIT1()   asm volatile("cp.async.wait_group 1;" ::: "memory")
#define CP_WAIT0()   asm volatile("cp.async.wait_group 0;" ::: "memory")

// ---------------- fused embed + init + first rmsnorm (cur = start) ----------------
__global__ void embednorm_k(const int* __restrict__ ids, const int* __restrict__ start,
                            const float* __restrict__ emb, const float* __restrict__ n1,
                            float* __restrict__ x,
                            float* __restrict__ outh, float* __restrict__ outl) {
    int t = blockIdx.x;
    int d = threadIdx.x;          // 512
    __shared__ float red[512];
    if (t == 0 && d == 0) {
        g_cur[0] = start[0];
        g_cur[1] = start[1];
        #pragma unroll
        for (int i = 0; i < Cc+1; i++) g_accp[i] = 0.f;
        g_acclb = 0.f;
    }
    float v = emb[(size_t)ids[t]*Dd + d] * sqrtf((float)Dd);
    x[t*Dd + d] = v;
    red[d] = v*v;
    __syncthreads();
    for (int s = 256; s > 0; s >>= 1) {
        if (d < s) red[d] += red[d+s];
        __syncthreads();
    }
    float scale = rsqrtf(red[0] * (1.0f/Dd) + 1e-6f);
    float o = v * scale * n1[(size_t)start[t / Ss] * Dd + d];
    split_store(o, &outh[t*Dd + d], &outl[t*Dd + d]);
}

// ---------------- rmsnorm (block per token), hi/lo output ----------------
__global__ void rmsnorm_k(const float* __restrict__ x, const float* __restrict__ w,
                          const int* __restrict__ cur,
                          float* __restrict__ outh, float* __restrict__ outl) {
    int t = blockIdx.x;
    int d = threadIdx.x;          // 512
    __shared__ float red[512];
    float v = x[t*Dd + d];
    red[d] = v*v;
    __syncthreads();
    for (int s = 256; s > 0; s >>= 1) {
        if (d < s) red[d] += red[d+s];
        __syncthreads();
    }
    float scale = rsqrtf(red[0] * (1.0f/Dd) + 1e-6f);
    const float* ww = w;
    if (cur) ww += (size_t)cur[t / Ss] * Dd;
    float o = v * scale * ww[d];
    split_store(o, &outh[t*Dd + d], &outl[t*Dd + d]);
}

// ---------------- tensor-core logits GEMM (A pre-converted to tf32 hi) ------
#define TC_SMEM ((2*128*36 + 2*32*136) * (int)sizeof(float))
__global__ void __launch_bounds__(256,2) gemm_tc(
    const float* __restrict__ A, const float* __restrict__ W,
    float* __restrict__ Out, int K, int N, int aux_n)
{
    extern __shared__ float dsm[];
    float (*As)[128][36]  = (float(*)[128][36])dsm;
    float (*Bs)[32][136]  = (float(*)[32][136])(dsm + 2*128*36);
    int tid = threadIdx.x;
    int m0 = blockIdx.x*128, n0 = blockIdx.y*128;
    int warp = tid >> 5, lane = tid & 31;
    int wm = warp & 1, wn = warp >> 1;
    int g = lane >> 2, tg = lane & 3;

    if (blockIdx.x == 0 && blockIdx.y == 0 && tid == 0 && aux_n > 0) {
        float avg[Cc+1];
        float m = 0.f;
        #pragma unroll
        for (int i = 0; i < Cc+1; i++) { avg[i] = g_accp[i] * 0.25f; m += avg[i]; }
        m *= 1.f/(Cc+1);
        float var = 0.f;
        #pragma unroll
        for (int i = 0; i < Cc+1; i++) { float d = avg[i] - m; var += d*d; }
        var *= 1.f/(Cc+1);
        Out[aux_n-2] = var;
        Out[aux_n-1] = g_acclb * 0.5f;
    }

    auto issue = [&](int k0, int buf) {
        #pragma unroll
        for (int l = 0; l < 4; l++) {
            int idx = tid + l*256;
            int row = idx >> 3, kc = (idx & 7) * 4;
            cp_async16(&As[buf][row][kc], &A[(size_t)(m0+row)*K + k0 + kc]);
        }
        #pragma unroll
        for (int l = 0; l < 4; l++) {
            int idx = tid + l*256;
            int kr = idx >> 5, nc = (idx & 31) * 4;
            cp_async16(&Bs[buf][kr][nc], &W[(size_t)(k0+kr)*N + n0 + nc]);
        }
        CP_COMMIT();
    };

    float acc[4][4][4] = {};
    int nk = K / 32;
    issue(0, 0);
    int buf = 0;
    for (int it = 0; it < nk; it++) {
        bool more = (it + 1) < nk;
        if (more) issue((it+1)*32, buf^1);
        if (more) CP_WAIT1(); else CP_WAIT0();
        __syncthreads();

        #pragma unroll
        for (int kk = 0; kk < 32; kk += 8) {
            uint32_t af[4][4], bf[4][2];
            #pragma unroll
            for (int mt = 0; mt < 4; mt++) {
                int mrow = wm*64 + mt*16 + g;
                af[mt][0] = __float_as_uint(As[buf][mrow  ][kk+tg]);
                af[mt][1] = __float_as_uint(As[buf][mrow+8][kk+tg]);
                af[mt][2] = __float_as_uint(As[buf][mrow  ][kk+tg+4]);
                af[mt][3] = __float_as_uint(As[buf][mrow+8][kk+tg+4]);
            }
            #pragma unroll
            for (int nt = 0; nt < 4; nt++) {
                int ncol = wn*32 + nt*8 + g;
                bf[nt][0] = f2tf32(Bs[buf][kk+tg  ][ncol]);
                bf[nt][1] = f2tf32(Bs[buf][kk+tg+4][ncol]);
            }
            #pragma unroll
            for (int mt = 0; mt < 4; mt++)
                #pragma unroll
                for (int nt = 0; nt < 4; nt++)
                    mma_tf32(acc[mt][nt], af[mt][0], af[mt][1], af[mt][2], af[mt][3],
                             bf[nt][0], bf[nt][1]);
        }
        __syncthreads();
        buf ^= 1;
    }

    #pragma unroll
    for (int mt = 0; mt < 4; mt++) {
        #pragma unroll
        for (int nt = 0; nt < 4; nt++) {
            int row = m0 + wm*64 + mt*16 + g;
            int col = n0 + wn*32 + nt*8 + 2*tg;
            float2 lo = { acc[mt][nt][0], acc[mt][nt][1] };
            float2 hi = { acc[mt][nt][2], acc[mt][nt][3] };
            *(float2*)&Out[(size_t)row*N + col]     = lo;
            *(float2*)&Out[(size_t)(row+8)*N + col] = hi;
        }
    }
}

// ---------------- tf32x3 mid GEMM core, A pre-split, 3 independent acc banks ----
#define TC64_SMEM (13824 * (int)sizeof(float))
__device__ __forceinline__ void tc64_core(
    const float* __restrict__ Ah, const float* __restrict__ Al, int lda,
    const float* __restrict__ W,
    int K, int N, int m0, int n0, int tid, float acc[2][2][4], float* sm)
{
    float (*AsH)[64][36] = (float(*)[64][36])sm;
    float (*AsL)[64][36] = (float(*)[64][36])(sm + 2*64*36);
    float (*Bs)[32][72]  = (float(*)[32][72])(sm + 4*64*36);
    int warp = tid >> 5, lane = tid & 31;
    int wm = warp & 1, wn = warp >> 1;
    int g = lane >> 2, tg = lane & 3;

    auto issue = [&](int k0, int buf) {
        #pragma unroll
        for (int l = 0; l < 2; l++) {
            int idx = tid + l*256;
            int row = idx >> 3, kc = (idx & 7) * 4;
            size_t goff = (size_t)(m0+row)*lda + k0 + kc;
            cp_async16(&AsH[buf][row][kc], &Ah[goff]);
            cp_async16(&AsL[buf][row][kc], &Al[goff]);
        }
        #pragma unroll
        for (int l = 0; l < 2; l++) {
            int idx = tid + l*256;
            int kr = idx >> 4, nc = (idx & 15) * 4;
            cp_async16(&Bs[buf][kr][nc], &W[(size_t)(k0+kr)*N + n0 + nc]);
        }
        CP_COMMIT();
    };

    float a3[3][2][2][4] = {};

    int nk = K / 32;
    issue(0, 0);
    int buf = 0;
    for (int it = 0; it < nk; it++) {
        bool more = (it + 1) < nk;
        if (more) issue((it+1)*32, buf^1);
        if (more) CP_WAIT1(); else CP_WAIT0();
        __syncthreads();

        #pragma unroll
        for (int kk = 0; kk < 32; kk += 8) {
            uint32_t ah[2][4], al[2][4], bh[2][2], bl[2][2];
            #pragma unroll
            for (int mt = 0; mt < 2; mt++) {
                int mrow = wm*32 + mt*16 + g;
                ah[mt][0] = __float_as_uint(AsH[buf][mrow  ][kk+tg]);
                ah[mt][1] = __float_as_uint(AsH[buf][mrow+8][kk+tg]);
                ah[mt][2] = __float_as_uint(AsH[buf][mrow  ][kk+tg+4]);
                ah[mt][3] = __float_as_uint(AsH[buf][mrow+8][kk+tg+4]);
                al[mt][0] = __float_as_uint(AsL[buf][mrow  ][kk+tg]);
                al[mt][1] = __float_as_uint(AsL[buf][mrow+8][kk+tg]);
                al[mt][2] = __float_as_uint(AsL[buf][mrow  ][kk+tg+4]);
                al[mt][3] = __float_as_uint(AsL[buf][mrow+8][kk+tg+4]);
            }
            #pragma unroll
            for (int nt = 0; nt < 2; nt++) {
                int ncol = wn*16 + nt*8 + g;
                float b0 = Bs[buf][kk+tg  ][ncol];
                float b1 = Bs[buf][kk+tg+4][ncol];
                bh[nt][0] = f2tf32(b0); bl[nt][0] = f2tf32(b0 - __uint_as_float(bh[nt][0]));
                bh[nt][1] = f2tf32(b1); bl[nt][1] = f2tf32(b1 - __uint_as_float(bh[nt][1]));
            }
            #pragma unroll
            for (int mt = 0; mt < 2; mt++)
                #pragma unroll
                for (int nt = 0; nt < 2; nt++) {
                    mma_tf32(a3[0][mt][nt], ah[mt][0], ah[mt][1], ah[mt][2], ah[mt][3],
                             bl[nt][0], bl[nt][1]);
                    mma_tf32(a3[1][mt][nt], al[mt][0], al[mt][1], al[mt][2], al[mt][3],
                             bh[nt][0], bh[nt][1]);
                    mma_tf32(a3[2][mt][nt], ah[mt][0], ah[mt][1], ah[mt][2], ah[mt][3],
                             bh[nt][0], bh[nt][1]);
                }
        }
        __syncthreads();
        buf ^= 1;
    }

    #pragma unroll
    for (int mt = 0; mt < 2; mt++)
        #pragma unroll
        for (int nt = 0; nt < 2; nt++)
            #pragma unroll
            for (int c = 0; c < 4; c++)
                acc[mt][nt][c] = a3[2][mt][nt][c] + (a3[0][mt][nt][c] + a3[1][mt][nt][c]);
}

// shared epilogue. epi: 0 store, 1 res+acc, 2 silu, 3 silu+split-store(Out=hi, Out2=lo)
__device__ __forceinline__ void tc64_epilogue(
    float acc[2][2][4], const float* __restrict__ res,
    float* __restrict__ Out, float* __restrict__ Out2,
    int N, int m0, int n0, int tid, int epi)
{
    int warp = tid >> 5, lane = tid & 31;
    int wm = warp & 1, wn = warp >> 1;
    int g = lane >> 2, tg = lane & 3;
    #pragma unroll
    for (int mt = 0; mt < 2; mt++) {
        #pragma unroll
        for (int nt = 0; nt < 2; nt++) {
            int row = m0 + wm*32 + mt*16 + g;
            int col = n0 + wn*16 + nt*8 + 2*tg;
            float2 lo = { acc[mt][nt][0], acc[mt][nt][1] };
            float2 hi = { acc[mt][nt][2], acc[mt][nt][3] };
            if (epi == 1) {
                float2 r0 = *(const float2*)&res[(size_t)row*N + col];
                float2 r1 = *(const float2*)&res[(size_t)(row+8)*N + col];
                lo.x += r0.x; lo.y += r0.y;
                hi.x += r1.x; hi.y += r1.y;
            } else if (epi >= 2) {
                lo.x = lo.x / (1.f + expf(-lo.x));
                lo.y = lo.y / (1.f + expf(-lo.y));
                hi.x = hi.x / (1.f + expf(-hi.x));
                hi.y = hi.y / (1.f + expf(-hi.y));
            }
            if (epi == 3) {
                size_t r0i = (size_t)row*N + col, r1i = (size_t)(row+8)*N + col;
                float2 loh, lol, hih, hil;
                uint32_t u;
                u = f2tf32(lo.x); loh.x = __uint_as_float(u); lol.x = __uint_as_float(f2tf32(lo.x - loh.x));
                u = f2tf32(lo.y); loh.y = __uint_as_float(u); lol.y = __uint_as_float(f2tf32(lo.y - loh.y));
                u = f2tf32(hi.x); hih.x = __uint_as_float(u); hil.x = __uint_as_float(f2tf32(hi.x - hih.x));
                u = f2tf32(hi.y); hih.y = __uint_as_float(u); hil.y = __uint_as_float(f2tf32(hi.y - hih.y));
                *(float2*)&Out [r0i] = loh; *(float2*)&Out2[r0i] = lol;
                *(float2*)&Out [r1i] = hih; *(float2*)&Out2[r1i] = hil;
            } else {
                *(float2*)&Out[(size_t)row*N + col]     = lo;
                *(float2*)&Out[(size_t)(row+8)*N + col] = hi;
            }
        }
    }
}

// ---------------- mid GEMM, direct (used for W1: epi=3 silu+split) ----------------
__global__ void __launch_bounds__(256) gemm_mid_tc(
    const float* __restrict__ Ah, const float* __restrict__ Al,
    const float* __restrict__ Wb,
    const float* __restrict__ res, float* __restrict__ Out, float* __restrict__ Out2,
    const int* __restrict__ cur, int K, int N, int epi)
{
    extern __shared__ float sm[];
    int m0 = blockIdx.y*64, n0 = blockIdx.x*64;
    const float* W = Wb;
    if (cur) W += (size_t)cur[m0 / Ss] * K * N;
    float acc[2][2][4] = {};
    tc64_core(Ah, Al, K, W, K, N, m0, n0, threadIdx.x, acc, sm);
    tc64_epilogue(acc, res, Out, Out2, N, m0, n0, threadIdx.x, epi);
}

// ---------------- split-K mid GEMM -> partials (N = Dd) ----------------
__global__ void __launch_bounds__(256) gemm_sk(
    const float* __restrict__ Ah, const float* __restrict__ Al, int lda,
    const float* __restrict__ Wb,
    float* __restrict__ part, const int* __restrict__ cur, int Kfull, int klen)
{
    extern __shared__ float sm[];
    int m0 = blockIdx.y*64, n0 = blockIdx.x*64;
    int z = blockIdx.z;
    const float* W = Wb + (size_t)cur[m0 / Ss] * Kfull * Dd + (size_t)z * klen * Dd;
    float acc[2][2][4] = {};
    tc64_core(Ah + (size_t)z * klen, Al + (size_t)z * klen, lda, W, klen, Dd,
              m0, n0, threadIdx.x, acc, sm);
    tc64_epilogue(acc, nullptr, part + (size_t)z * TOK * Dd, nullptr, Dd, m0, n0, threadIdx.x, 0);
}

// ---------------- split-K QKV -> 6 partials ----------------
__global__ void __launch_bounds__(256) qkv_sk(
    const float* __restrict__ xnh, const float* __restrict__ xnl,
    const float* __restrict__ Wq, const float* __restrict__ Wk, const float* __restrict__ Wv,
    float* __restrict__ part, const int* __restrict__ cur)
{
    extern __shared__ float sm[];
    int z = blockIdx.z;
    int op = z >> 1, half = z & 1;
    const float* Wb = (op == 0) ? Wq : (op == 1) ? Wk : Wv;
    int m0 = blockIdx.y*64, n0 = blockIdx.x*64;
    const float* W = Wb + (size_t)cur[m0 / Ss] * Dd * Dd + (size_t)half * 256 * Dd;
    float acc[2][2][4] = {};
    tc64_core(xnh + (size_t)half * 256, xnl + (size_t)half * 256, Dd, W, 256, Dd,
              m0, n0, threadIdx.x, acc, sm);
    tc64_epilogue(acc, nullptr, part + (size_t)z * TOK * Dd, nullptr, Dd, m0, n0, threadIdx.x, 0);
}

// ---------------- fused qkv reduce (2 partials each) + rope ----------------
__global__ void qkvrope_k(const float* __restrict__ part,
                          float* __restrict__ q, float* __restrict__ k, float* __restrict__ v) {
    int t = blockIdx.x;
    int s = t % Ss;
    int i = threadIdx.x;
    int base = t*Dd + 2*i;
    float q0=0, q1=0, k0=0, k1=0, v0=0, v1=0;
    #pragma unroll
    for (int z = 0; z < 2; z++) {
        const float* pq = part + (size_t)z      * TOK*Dd + base;
        const float* pk = part + (size_t)(2+z)  * TOK*Dd + base;
        const float* pv = part + (size_t)(4+z)  * TOK*Dd + base;
        q0 += pq[0]; q1 += pq[1];
        k0 += pk[0]; k1 += pk[1];
        v0 += pv[0]; v1 += pv[1];
    }
    int j = i & 31;
    float inv = powf(10000.f, -(2.f*j) / 64.f);
    float ang = (float)s * inv;
    float c = cosf(ang), sn = sinf(ang);
    q[base]   = q0*c - q1*sn;
    q[base+1] = q0*sn + q1*c;
    k[base]   = k0*c - k1*sn;
    k[base+1] = k0*sn + k1*c;
    v[base]   = v0;
    v[base+1] = v1;
}

// ---------------- fused Wo reduce (2 partials) + residual + rmsnorm(n2) ------
__global__ void rednorm_k(float* __restrict__ x, const float* __restrict__ part,
                          const float* __restrict__ w, const int* __restrict__ cur,
                          float* __restrict__ outh, float* __restrict__ outl) {
    int t = blockIdx.x;
    int d = threadIdx.x;          // 512
    __shared__ float red[512];
    int idx = t*Dd + d;
    float v = x[idx];
    #pragma unroll
    for (int z = 0; z < 2; z++) v += part[(size_t)z*TOK*Dd + idx];
    x[idx] = v;
    red[d] = v*v;
    __syncthreads();
    for (int s = 256; s > 0; s >>= 1) {
        if (d < s) red[d] += red[d+s];
        __syncthreads();
    }
    float scale = rsqrtf(red[0] * (1.0f/Dd) + 1e-6f);
    float o = v * scale * w[(size_t)cur[t / Ss] * Dd + d];
    split_store(o, &outh[idx], &outl[idx]);
}

// ---------------- reduce: x += sum of S partials ----------------
__global__ void red_add(float* __restrict__ x, const float* __restrict__ part, int S) {
    int i = blockIdx.x*256 + threadIdx.x;
    float s = x[i];
    for (int j = 0; j < S; j++) s += part[(size_t)j*TOK*Dd + i];
    x[i] = s;
}

// ---------------- split-K flash attention: partial kernel ----------------
// grid (4, Hh, Bb*8): kt = blockIdx.x, h = blockIdx.y, b = z>>3, qt = z&7.
// Inactive (kt > qt/2) blocks exit. R13-exact inner loops on one k-tile.
#define ATT_SMEM ((32*68 + 64*68 + 64*68 + 32*68) * (int)sizeof(float))
__global__ void __launch_bounds__(256) fattn_part(
    const float* __restrict__ q, const float* __restrict__ k,
    const float* __restrict__ v,
    float* __restrict__ opart, float* __restrict__ ml)
{
    int kt = blockIdx.x, h = blockIdx.y;
    int b = blockIdx.z >> 3, qt = blockIdx.z & 7;
    if (kt > (qt >> 1)) return;
    extern __shared__ float asm_[];
    float (*Qs)[68] = (float(*)[68])asm_;
    float (*Ks)[68] = (float(*)[68])(asm_ + 32*68);
    float (*Vs)[68] = (float(*)[68])(asm_ + 32*68 + 64*68);
    float (*Ps)[68] = (float(*)[68])(asm_ + 32*68 + 2*64*68);
    int tid = threadIdx.x;
    int row = tid >> 3;           // 0..31
    int sub = tid & 7;            // 0..7
    int base_bh = b*Ss*Dd + h*HD;
    int gq = qt*32 + row;

    // load Q tile (32 x 64) and K,V tile (64 x 64 each)
    #pragma unroll
    for (int l = 0; l < 2; l++) {
        int idx = tid + l*256;
        int r = idx >> 4;
        int c = (idx & 15) * 4;
        *(float4*)&Qs[r][c] = *(const float4*)&q[base_bh + (qt*32 + r)*Dd + c];
    }
    #pragma unroll
    for (int l = 0; l < 4; l++) {
        int idx = tid + l*256;
        int r = idx >> 4;
        int c = (idx & 15) * 4;
        *(float4*)&Ks[r][c] = *(const float4*)&k[base_bh + (kt*64 + r)*Dd + c];
        *(float4*)&Vs[r][c] = *(const float4*)&v[base_bh + (kt*64 + r)*Dd + c];
    }
    __syncthreads();

    // scores (R13 pattern: scalar, conflict-free)
    float s[8];
    #pragma unroll
    for (int jj = 0; jj < 8; jj++) s[jj] = 0.f;
    for (int d = 0; d < HD; d++) {
        float qd = Qs[row][d];
        #pragma unroll
        for (int jj = 0; jj < 8; jj++)
            s[jj] = fmaf(qd, Ks[sub + jj*8][d], s[jj]);
    }
    int kbase = kt*64;
    float mt_ = -1e30f;
    #pragma unroll
    for (int jj = 0; jj < 8; jj++) {
        int jg = kbase + sub + jj*8;
        s[jj] = (jg <= gq) ? s[jj]*0.125f : -1e30f;
        mt_ = fmaxf(mt_, s[jj]);
    }
    mt_ = fmaxf(mt_, __shfl_xor_sync(0xffffffffu, mt_, 1));
    mt_ = fmaxf(mt_, __shfl_xor_sync(0xffffffffu, mt_, 2));
    mt_ = fmaxf(mt_, __shfl_xor_sync(0xffffffffu, mt_, 4));
    float lt = 0.f;
    #pragma unroll
    for (int jj = 0; jj < 8; jj++) {
        float p = expf(s[jj] - mt_);
        Ps[row][sub + jj*8] = p;
        lt += p;
    }
    lt += __shfl_xor_sync(0xffffffffu, lt, 1);
    lt += __shfl_xor_sync(0xffffffffu, lt, 2);
    lt += __shfl_xor_sync(0xffffffffu, lt, 4);
    __syncwarp();                 // Ps row produced/consumed within one warp

    // unnormalized O for this tile (thread owns d = sub + 8t)
    float Oacc[8];
    #pragma unroll
    for (int t = 0; t < 8; t++) Oacc[t] = 0.f;
    for (int j = 0; j < 64; j++) {
        float pj = Ps[row][j];
        #pragma unroll
        for (int t = 0; t < 8; t++)
            Oacc[t] = fmaf(pj, Vs[j][sub + 8*t], Oacc[t]);
    }

    // store partial
    int pidx = (((b*Hh + h)*8 + qt)*4 + kt);
    float* op = opart + (size_t)pidx * 32 * 64 + row*64;
    #pragma unroll
    for (int t = 0; t < 8; t++) op[sub + 8*t] = Oacc[t];
    if (sub == 0) {
        ml[pidx*64 + row*2]     = mt_;
        ml[pidx*64 + row*2 + 1] = lt;
    }
}

// ---------------- split-K flash attention: merge kernel ----------------
// grid (8, Hh, Bb), 256 threads: row = tid>>3, d = sub + 8t.
__global__ void __launch_bounds__(256) fattn_merge(
    const float* __restrict__ opart, const float* __restrict__ ml,
    float* __restrict__ oh, float* __restrict__ ol)
{
    int qt = blockIdx.x, h = blockIdx.y, b = blockIdx.z;
    int tid = threadIdx.x;
    int row = tid >> 3;
    int sub = tid & 7;
    int nkt = (qt >> 1) + 1;
    int pbase = ((b*Hh + h)*8 + qt)*4;

    float M = -1e30f;
    for (int kt = 0; kt < nkt; kt++)
        M = fmaxf(M, ml[(pbase+kt)*64 + row*2]);
    float L = 0.f;
    float Oacc[8];
    #pragma unroll
    for (int t = 0; t < 8; t++) Oacc[t] = 0.f;
    for (int kt = 0; kt < nkt; kt++) {
        float mi = ml[(pbase+kt)*64 + row*2];
        float li = ml[(pbase+kt)*64 + row*2 + 1];
        float w = expf(mi - M);
        L += li * w;
        const float* op = opart + (size_t)(pbase+kt) * 32 * 64 + row*64;
        #pragma unroll
        for (int t = 0; t < 8; t++)
            Oacc[t] = fmaf(w, op[sub + 8*t], Oacc[t]);
    }
    float inv = 1.f / L;
    int base_bh = b*Ss*Dd + h*HD;
    int gq = qt*32 + row;
    #pragma unroll
    for (int t = 0; t < 8; t++) {
        float vo = Oacc[t] * inv;
        size_t idx = base_bh + (size_t)gq*Dd + sub + 8*t;
        split_store(vo, &oh[idx], &ol[idx]);
    }
}

// ---------------- parallel pooling ----------------
__global__ void pool_k(const float* __restrict__ x, float* __restrict__ pooled) {
    int b = blockIdx.y;
    int d = blockIdx.x*128 + threadIdx.x;
    float s = 0.f;
    #pragma unroll 4
    for (int ss = 0; ss < Ss; ss++) s += x[(size_t)(b*Ss+ss)*Dd + d];
    pooled[b*Dd + d] = s * (1.f/Ss);
}

// ---------------- gating + routing (single block, reads pooled) ----------------
__global__ void gate_k(const float* __restrict__ pooled, const float* __restrict__ gw) {
    __shared__ float red[512];
    __shared__ float sc[2*(Cc+1)];
    int tid = threadIdx.x;
    for (int idx = 0; idx < 2*(Cc+1); idx++) {
        int b = idx / (Cc+1), c = idx % (Cc+1);
        red[tid] = pooled[b*Dd + tid] * gw[tid*(Cc+1) + c];
        __syncthreads();
        for (int s = 256; s > 0; s >>= 1) {
            if (tid < s) red[tid] += red[tid+s];
            __syncthreads();
        }
        if (tid == 0) sc[idx] = red[0];
        __syncthreads();
    }
    if (tid == 0) {
        float p[Bb][Cc+1];
        for (int b = 0; b < Bb; b++) {
            float mx = -1e30f;
            for (int c = 0; c < Cc+1; c++) mx = fmaxf(mx, sc[b*(Cc+1)+c]);
            float sum = 0.f;
            for (int c = 0; c < Cc+1; c++) { p[b][c] = expf(sc[b*(Cc+1)+c] - mx); sum += p[b][c]; }
            for (int c = 0; c < Cc+1; c++) p[b][c] /= sum;
        }
        float lb = 0.f;
        for (int c = 0; c < Cc+1; c++) {
            g_accp[c] += p[0][c] + p[1][c];
            float avg = 0.5f * (p[0][c] + p[1][c]);
            lb += avg*avg;
        }
        g_acclb += (float)(Cc+1) * lb;
        for (int b = 0; b < Bb; b++) {
            int co = g_cur[b];
            int j1 = (co+1) & 3, j2 = (co+2) & 3;
            float s1 = sc[b*(Cc+1)+j1], s2 = sc[b*(Cc+1)+j2];
            int w;
            if (s1 > s2) w = j1;
            else if (s2 > s1) w = j2;
            else w = (j1 < j2) ? j1 : j2;
            g_cur[b] = w;
        }
    }
}

// ---------------- host orchestration ----------------
extern "C" void kernel_launch(void* const* d_in, const int* in_sizes, int n_in,
                              void* d_out, int out_size) {
    const int*   ids   = (const int*)  d_in[0];
    const int*   start = (const int*)  d_in[1];
    const float* emb   = (const float*)d_in[2];
    const float* Wq    = (const float*)d_in[3];
    const float* Wk    = (const float*)d_in[4];
    const float* Wv    = (const float*)d_in[5];
    const float* Wo    = (const float*)d_in[6];
    const float* W1    = (const float*)d_in[7];
    const float* W2    = (const float*)d_in[8];
    const float* n1    = (const float*)d_in[9];
    const float* n2    = (const float*)d_in[10];
    const float* gw    = (const float*)d_in[11];
    const float* fnw   = (const float*)d_in[12];
    const float* fcw   = (const float*)d_in[13];
    float* out = (float*)d_out;

    float *x, *xnh, *xnl, *q, *k, *v, *oh, *ol, *ffh, *ffl, *part, *pool, *att, *ml;
    int* cur;
    cudaGetSymbolAddress((void**)&x,   g_x);
    cudaGetSymbolAddress((void**)&xnh, g_xnh);
    cudaGetSymbolAddress((void**)&xnl, g_xnl);
    cudaGetSymbolAddress((void**)&q,   g_q);
    cudaGetSymbolAddress((void**)&k,   g_k);
    cudaGetSymbolAddress((void**)&v,   g_v);
    cudaGetSymbolAddress((void**)&oh,  g_oh);
    cudaGetSymbolAddress((void**)&ol,  g_ol);
    cudaGetSymbolAddress((void**)&ffh, g_ffh);
    cudaGetSymbolAddress((void**)&ffl, g_ffl);
    cudaGetSymbolAddress((void**)&part, g_part);
    cudaGetSymbolAddress((void**)&att, g_att);
    cudaGetSymbolAddress((void**)&ml,  g_ml);
    cudaGetSymbolAddress((void**)&pool, g_pool);
    cudaGetSymbolAddress((void**)&cur, g_cur);

    static int smem_set = 0;
    if (!smem_set) {
        cudaFuncSetAttribute(gemm_tc,    cudaFuncAttributeMaxDynamicSharedMemorySize, TC_SMEM);
        cudaFuncSetAttribute(fattn_part, cudaFuncAttributeMaxDynamicSharedMemorySize, ATT_SMEM);
        cudaFuncSetAttribute(qkv_sk,     cudaFuncAttributeMaxDynamicSharedMemorySize, TC64_SMEM);
        cudaFuncSetAttribute(gemm_sk,    cudaFuncAttributeMaxDynamicSharedMemorySize, TC64_SMEM);
        cudaFuncSetAttribute(gemm_mid_tc,cudaFuncAttributeMaxDynamicSharedMemorySize, TC64_SMEM);
        smem_set = 1;
    }

    embednorm_k<<<TOK, Dd>>>(ids, start, emb, n1, x, xnh, xnl);

    int nred = TOK*Dd/256;            // 1024 blocks
    dim3 gqkv(Dd/64, TOK/64, 6);      // 384 blocks (split-K=2 x q,k,v)
    dim3 gwo (Dd/64, TOK/64, 2);      // 128 blocks (split-K=2)
    dim3 gw1 (Ff/64, TOK/64);         // 256 blocks
    dim3 gw2 (Dd/64, TOK/64, 4);      // 256 blocks (split-K=4)
    dim3 gap (4, Hh, Bb*8);           // 512 blocks (320 active)
    dim3 gam (8, Hh, Bb);             // 128 blocks
    for (int step = 0; step < 2; step++) {
        if (step > 0)
            rmsnorm_k<<<TOK, Dd>>>(x, n1, cur, xnh, xnl);
        qkv_sk<<<gqkv, 256, TC64_SMEM>>>(xnh, xnl, Wq, Wk, Wv, part, cur);
        qkvrope_k<<<TOK, 256>>>(part, q, k, v);
        fattn_part<<<gap, 256, ATT_SMEM>>>(q, k, v, att, ml);
        fattn_merge<<<gam, 256>>>(att, ml, oh, ol);
        gemm_sk<<<gwo, 256, TC64_SMEM>>>(oh, ol, Dd, Wo, part, cur, Dd, 256);
        rednorm_k<<<TOK, Dd>>>(x, part, n2, cur, xnh, xnl);
        gemm_mid_tc<<<gw1, 256, TC64_SMEM>>>(xnh, xnl, W1, nullptr, ffh, ffl, cur, Dd, Ff, 3);
        gemm_sk<<<gw2, 256, TC64_SMEM>>>(ffh, ffl, Ff, W2, part, cur, Ff, 512);
        red_add<<<nred, 256>>>(x, part, 4);
        pool_k<<<dim3(Dd/128, Bb), 128>>>(x, pool);
        gate_k<<<1, 512>>>(pool, gw);
    }
    rmsnorm_k<<<TOK, Dd>>>(x, fnw, nullptr, xnh, xnl);
    gemm_tc<<<dim3(TOK/128, Vv/128), 256, TC_SMEM>>>(xnh, fcw, out, Dd, Vv, out_size);
}

// round 17
// speedup vs baseline: 1.2657x; 1.2657x over previous
#include <cuda_runtime.h>
#include <math.h>
#include <stdint.h>

#define Dd  512
#define Hh  8
#define HD  64
#define Bb  2
#define Ss  256
#define Ff  2048
#define Cc  4
#define Vv  32000
#define TOK (Bb*Ss)   // 512

// ---------------- device state (no allocation allowed) ----------------
__device__ float g_x  [TOK*Dd];
__device__ float g_xn [TOK*Dd];    // tf32-rounded activations
__device__ float g_q  [TOK*Dd];
__device__ float g_k  [TOK*Dd];
__device__ float g_v  [TOK*Dd];
__device__ float g_o  [TOK*Dd];    // tf32-rounded attention out
__device__ float g_ff [TOK*Ff];    // tf32-rounded ffn mid
__device__ float g_part[6*TOK*Dd];
__device__ float g_pool[Bb*Dd];
__device__ int   g_cur[Bb];
__device__ float g_accp[Cc+1];
__device__ float g_acclb;

// ---------------- tf32 / cp.async helpers ----------------
__device__ __forceinline__ uint32_t f2tf32(float f) {
    uint32_t u;
    asm volatile("cvt.rna.tf32.f32 %0, %1;" : "=r"(u) : "f"(f));
    return u;
}

__device__ __forceinline__ void mma_tf32(float c[4],
    uint32_t a0, uint32_t a1, uint32_t a2, uint32_t a3,
    uint32_t b0, uint32_t b1)
{
    asm volatile(
        "mma.sync.aligned.m16n8k8.row.col.f32.tf32.tf32.f32 "
        "{%0,%1,%2,%3}, {%4,%5,%6,%7}, {%8,%9}, {%0,%1,%2,%3};"
        : "+f"(c[0]), "+f"(c[1]), "+f"(c[2]), "+f"(c[3])
        : "r"(a0), "r"(a1), "r"(a2), "r"(a3), "r"(b0), "r"(b1));
}

__device__ __forceinline__ void cp_async16(float* smem, const float* gmem) {
    uint32_t s;
    asm("{ .reg .u64 t; cvta.to.shared.u64 t, %1; cvt.u32.u64 %0, t; }"
        : "=r"(s) : "l"(smem));
    asm volatile("cp.async.cg.shared.global [%0], [%1], 16;" :: "r"(s), "l"(gmem) : "memory");
}
#define CP_COMMIT()  asm volatile("cp.async.commit_group;" ::: "memory")
#define CP_WAIT1()   asm volatile("cp.async.wait_group 1;" ::: "memory")
#define CP_WAIT0()   asm volatile("cp.async.wait_group 0;" ::: "memory")

// ---------------- fused embed + init + first rmsnorm (cur = start) ----------------
__global__ void embednorm_k(const int* __restrict__ ids, const int* __restrict__ start,
                            const float* __restrict__ emb, const float* __restrict__ n1,
                            float* __restrict__ x, float* __restrict__ out) {
    int t = blockIdx.x;
    int d = threadIdx.x;          // 512
    __shared__ float red[512];
    if (t == 0 && d == 0) {
        g_cur[0] = start[0];
        g_cur[1] = start[1];
        #pragma unroll
        for (int i = 0; i < Cc+1; i++) g_accp[i] = 0.f;
        g_acclb = 0.f;
    }
    float v = emb[(size_t)ids[t]*Dd + d] * sqrtf((float)Dd);
    x[t*Dd + d] = v;
    red[d] = v*v;
    __syncthreads();
    for (int s = 256; s > 0; s >>= 1) {
        if (d < s) red[d] += red[d+s];
        __syncthreads();
    }
    float scale = rsqrtf(red[0] * (1.0f/Dd) + 1e-6f);
    float o = v * scale * n1[(size_t)start[t / Ss] * Dd + d];
    out[t*Dd + d] = __uint_as_float(f2tf32(o));
}

// ---------------- rmsnorm (block per token), tf32-rounded output ----------------
__global__ void rmsnorm_k(const float* __restrict__ x, const float* __restrict__ w,
                          const int* __restrict__ cur, float* __restrict__ out) {
    int t = blockIdx.x;
    int d = threadIdx.x;          // 512
    __shared__ float red[512];
    float v = x[t*Dd + d];
    red[d] = v*v;
    __syncthreads();
    for (int s = 256; s > 0; s >>= 1) {
        if (d < s) red[d] += red[d+s];
        __syncthreads();
    }
    float scale = rsqrtf(red[0] * (1.0f/Dd) + 1e-6f);
    const float* ww = w;
    if (cur) ww += (size_t)cur[t / Ss] * Dd;
    float o = v * scale * ww[d];
    out[t*Dd + d] = __uint_as_float(f2tf32(o));
}

// ---------------- tensor-core logits GEMM (A pre-rounded tf32) ------
#define TC_SMEM ((2*128*36 + 2*32*136) * (int)sizeof(float))
__global__ void __launch_bounds__(256,2) gemm_tc(
    const float* __restrict__ A, const float* __restrict__ W,
    float* __restrict__ Out, int K, int N, int aux_n)
{
    extern __shared__ float dsm[];
    float (*As)[128][36]  = (float(*)[128][36])dsm;
    float (*Bs)[32][136]  = (float(*)[32][136])(dsm + 2*128*36);
    int tid = threadIdx.x;
    int m0 = blockIdx.x*128, n0 = blockIdx.y*128;
    int warp = tid >> 5, lane = tid & 31;
    int wm = warp & 1, wn = warp >> 1;
    int g = lane >> 2, tg = lane & 3;

    if (blockIdx.x == 0 && blockIdx.y == 0 && tid == 0 && aux_n > 0) {
        float avg[Cc+1];
        float m = 0.f;
        #pragma unroll
        for (int i = 0; i < Cc+1; i++) { avg[i] = g_accp[i] * 0.25f; m += avg[i]; }
        m *= 1.f/(Cc+1);
        float var = 0.f;
        #pragma unroll
        for (int i = 0; i < Cc+1; i++) { float d = avg[i] - m; var += d*d; }
        var *= 1.f/(Cc+1);
        Out[aux_n-2] = var;
        Out[aux_n-1] = g_acclb * 0.5f;
    }

    auto issue = [&](int k0, int buf) {
        #pragma unroll
        for (int l = 0; l < 4; l++) {
            int idx = tid + l*256;
            int row = idx >> 3, kc = (idx & 7) * 4;
            cp_async16(&As[buf][row][kc], &A[(size_t)(m0+row)*K + k0 + kc]);
        }
        #pragma unroll
        for (int l = 0; l < 4; l++) {
            int idx = tid + l*256;
            int kr = idx >> 5, nc = (idx & 31) * 4;
            cp_async16(&Bs[buf][kr][nc], &W[(size_t)(k0+kr)*N + n0 + nc]);
        }
        CP_COMMIT();
    };

    float acc[4][4][4] = {};
    int nk = K / 32;
    issue(0, 0);
    int buf = 0;
    for (int it = 0; it < nk; it++) {
        bool more = (it + 1) < nk;
        if (more) issue((it+1)*32, buf^1);
        if (more) CP_WAIT1(); else CP_WAIT0();
        __syncthreads();

        #pragma unroll
        for (int kk = 0; kk < 32; kk += 8) {
            uint32_t af[4][4], bf[4][2];
            #pragma unroll
            for (int mt = 0; mt < 4; mt++) {
                int mrow = wm*64 + mt*16 + g;
                af[mt][0] = __float_as_uint(As[buf][mrow  ][kk+tg]);
                af[mt][1] = __float_as_uint(As[buf][mrow+8][kk+tg]);
                af[mt][2] = __float_as_uint(As[buf][mrow  ][kk+tg+4]);
                af[mt][3] = __float_as_uint(As[buf][mrow+8][kk+tg+4]);
            }
            #pragma unroll
            for (int nt = 0; nt < 4; nt++) {
                int ncol = wn*32 + nt*8 + g;
                bf[nt][0] = f2tf32(Bs[buf][kk+tg  ][ncol]);
                bf[nt][1] = f2tf32(Bs[buf][kk+tg+4][ncol]);
            }
            #pragma unroll
            for (int mt = 0; mt < 4; mt++)
                #pragma unroll
                for (int nt = 0; nt < 4; nt++)
                    mma_tf32(acc[mt][nt], af[mt][0], af[mt][1], af[mt][2], af[mt][3],
                             bf[nt][0], bf[nt][1]);
        }
        __syncthreads();
        buf ^= 1;
    }

    #pragma unroll
    for (int mt = 0; mt < 4; mt++) {
        #pragma unroll
        for (int nt = 0; nt < 4; nt++) {
            int row = m0 + wm*64 + mt*16 + g;
            int col = n0 + wn*32 + nt*8 + 2*tg;
            float2 lo = { acc[mt][nt][0], acc[mt][nt][1] };
            float2 hi = { acc[mt][nt][2], acc[mt][nt][3] };
            *(float2*)&Out[(size_t)row*N + col]     = lo;
            *(float2*)&Out[(size_t)(row+8)*N + col] = hi;
        }
    }
}

// ---------------- single-pass tf32 mid GEMM core (A pre-rounded) ----------------
// smem: As[2][64][36] + Bs[2][32][72] = 9216 floats (36 KB)
#define TC64_SMEM (9216 * (int)sizeof(float))
__device__ __forceinline__ void tc64_core(
    const float* __restrict__ A, int lda, const float* __restrict__ W,
    int K, int N, int m0, int n0, int tid, float acc[2][2][4], float* sm)
{
    float (*As)[64][36] = (float(*)[64][36])sm;
    float (*Bs)[32][72] = (float(*)[32][72])(sm + 2*64*36);
    int warp = tid >> 5, lane = tid & 31;
    int wm = warp & 1, wn = warp >> 1;
    int g = lane >> 2, tg = lane & 3;

    auto issue = [&](int k0, int buf) {
        #pragma unroll
        for (int l = 0; l < 2; l++) {
            int idx = tid + l*256;
            int row = idx >> 3, kc = (idx & 7) * 4;
            cp_async16(&As[buf][row][kc], &A[(size_t)(m0+row)*lda + k0 + kc]);
        }
        #pragma unroll
        for (int l = 0; l < 2; l++) {
            int idx = tid + l*256;
            int kr = idx >> 4, nc = (idx & 15) * 4;
            cp_async16(&Bs[buf][kr][nc], &W[(size_t)(k0+kr)*N + n0 + nc]);
        }
        CP_COMMIT();
    };

    int nk = K / 32;
    issue(0, 0);
    int buf = 0;
    for (int it = 0; it < nk; it++) {
        bool more = (it + 1) < nk;
        if (more) issue((it+1)*32, buf^1);
        if (more) CP_WAIT1(); else CP_WAIT0();
        __syncthreads();

        #pragma unroll
        for (int kk = 0; kk < 32; kk += 8) {
            uint32_t a[2][4], b[2][2];
            #pragma unroll
            for (int mt = 0; mt < 2; mt++) {
                int mrow = wm*32 + mt*16 + g;
                a[mt][0] = __float_as_uint(As[buf][mrow  ][kk+tg]);
                a[mt][1] = __float_as_uint(As[buf][mrow+8][kk+tg]);
                a[mt][2] = __float_as_uint(As[buf][mrow  ][kk+tg+4]);
                a[mt][3] = __float_as_uint(As[buf][mrow+8][kk+tg+4]);
            }
            #pragma unroll
            for (int nt = 0; nt < 2; nt++) {
                int ncol = wn*16 + nt*8 + g;
                b[nt][0] = f2tf32(Bs[buf][kk+tg  ][ncol]);
                b[nt][1] = f2tf32(Bs[buf][kk+tg+4][ncol]);
            }
            #pragma unroll
            for (int mt = 0; mt < 2; mt++)
                #pragma unroll
                for (int nt = 0; nt < 2; nt++)
                    mma_tf32(acc[mt][nt], a[mt][0], a[mt][1], a[mt][2], a[mt][3],
                             b[nt][0], b[nt][1]);
        }
        __syncthreads();
        buf ^= 1;
    }
}

// epilogue. epi: 0 store, 1 res+acc, 2 silu+tf32-round store
__device__ __forceinline__ void tc64_epilogue(
    float acc[2][2][4], const float* __restrict__ res, float* __restrict__ Out,
    int N, int m0, int n0, int tid, int epi)
{
    int warp = tid >> 5, lane = tid & 31;
    int wm = warp & 1, wn = warp >> 1;
    int g = lane >> 2, tg = lane & 3;
    #pragma unroll
    for (int mt = 0; mt < 2; mt++) {
        #pragma unroll
        for (int nt = 0; nt < 2; nt++) {
            int row = m0 + wm*32 + mt*16 + g;
            int col = n0 + wn*16 + nt*8 + 2*tg;
            float2 lo = { acc[mt][nt][0], acc[mt][nt][1] };
            float2 hi = { acc[mt][nt][2], acc[mt][nt][3] };
            if (epi == 1) {
                float2 r0 = *(const float2*)&res[(size_t)row*N + col];
                float2 r1 = *(const float2*)&res[(size_t)(row+8)*N + col];
                lo.x += r0.x; lo.y += r0.y;
                hi.x += r1.x; hi.y += r1.y;
            } else if (epi == 2) {
                lo.x = __uint_as_float(f2tf32(lo.x / (1.f + expf(-lo.x))));
                lo.y = __uint_as_float(f2tf32(lo.y / (1.f + expf(-lo.y))));
                hi.x = __uint_as_float(f2tf32(hi.x / (1.f + expf(-hi.x))));
                hi.y = __uint_as_float(f2tf32(hi.y / (1.f + expf(-hi.y))));
            }
            *(float2*)&Out[(size_t)row*N + col]     = lo;
            *(float2*)&Out[(size_t)(row+8)*N + col] = hi;
        }
    }
}

// ---------------- mid GEMM, direct (used for W1: epi=2 silu+round) ----------------
__global__ void __launch_bounds__(256) gemm_mid_tc(
    const float* __restrict__ A, const float* __restrict__ Wb,
    const float* __restrict__ res, float* __restrict__ Out,
    const int* __restrict__ cur, int K, int N, int epi)
{
    extern __shared__ float sm[];
    int m0 = blockIdx.y*64, n0 = blockIdx.x*64;
    const float* W = Wb;
    if (cur) W += (size_t)cur[m0 / Ss] * K * N;
    float acc[2][2][4] = {};
    tc64_core(A, K, W, K, N, m0, n0, threadIdx.x, acc, sm);
    tc64_epilogue(acc, res, Out, N, m0, n0, threadIdx.x, epi);
}

// ---------------- split-K mid GEMM -> partials (N = Dd) ----------------
__global__ void __launch_bounds__(256) gemm_sk(
    const float* __restrict__ A, int lda, const float* __restrict__ Wb,
    float* __restrict__ part, const int* __restrict__ cur, int Kfull, int klen)
{
    extern __shared__ float sm[];
    int m0 = blockIdx.y*64, n0 = blockIdx.x*64;
    int z = blockIdx.z;
    const float* W = Wb + (size_t)cur[m0 / Ss] * Kfull * Dd + (size_t)z * klen * Dd;
    float acc[2][2][4] = {};
    tc64_core(A + (size_t)z * klen, lda, W, klen, Dd, m0, n0, threadIdx.x, acc, sm);
    tc64_epilogue(acc, nullptr, part + (size_t)z * TOK * Dd, Dd, m0, n0, threadIdx.x, 0);
}

// ---------------- split-K QKV -> 6 partials ----------------
__global__ void __launch_bounds__(256) qkv_sk(
    const float* __restrict__ xn,
    const float* __restrict__ Wq, const float* __restrict__ Wk, const float* __restrict__ Wv,
    float* __restrict__ part, const int* __restrict__ cur)
{
    extern __shared__ float sm[];
    int z = blockIdx.z;
    int op = z >> 1, half = z & 1;
    const float* Wb = (op == 0) ? Wq : (op == 1) ? Wk : Wv;
    int m0 = blockIdx.y*64, n0 = blockIdx.x*64;
    const float* W = Wb + (size_t)cur[m0 / Ss] * Dd * Dd + (size_t)half * 256 * Dd;
    float acc[2][2][4] = {};
    tc64_core(xn + (size_t)half * 256, Dd, W, 256, Dd, m0, n0, threadIdx.x, acc, sm);
    tc64_epilogue(acc, nullptr, part + (size_t)z * TOK * Dd, Dd, m0, n0, threadIdx.x, 0);
}

// ---------------- fused qkv reduce (2 partials each) + rope ----------------
__global__ void qkvrope_k(const float* __restrict__ part,
                          float* __restrict__ q, float* __restrict__ k, float* __restrict__ v) {
    int t = blockIdx.x;
    int s = t % Ss;
    int i = threadIdx.x;
    int base = t*Dd + 2*i;
    float q0=0, q1=0, k0=0, k1=0, v0=0, v1=0;
    #pragma unroll
    for (int z = 0; z < 2; z++) {
        const float* pq = part + (size_t)z      * TOK*Dd + base;
        const float* pk = part + (size_t)(2+z)  * TOK*Dd + base;
        const float* pv = part + (size_t)(4+z)  * TOK*Dd + base;
        q0 += pq[0]; q1 += pq[1];
        k0 += pk[0]; k1 += pk[1];
        v0 += pv[0]; v1 += pv[1];
    }
    int j = i & 31;
    float inv = powf(10000.f, -(2.f*j) / 64.f);
    float ang = (float)s * inv;
    float c = cosf(ang), sn = sinf(ang);
    q[base]   = q0*c - q1*sn;
    q[base+1] = q0*sn + q1*c;
    k[base]   = k0*c - k1*sn;
    k[base+1] = k0*sn + k1*c;
    v[base]   = v0;
    v[base+1] = v1;
}

// ---------------- fused Wo reduce (2 partials) + residual + rmsnorm(n2) ------
__global__ void rednorm_k(float* __restrict__ x, const float* __restrict__ part,
                          const float* __restrict__ w, const int* __restrict__ cur,
                          float* __restrict__ out) {
    int t = blockIdx.x;
    int d = threadIdx.x;          // 512
    __shared__ float red[512];
    int idx = t*Dd + d;
    float v = x[idx];
    #pragma unroll
    for (int z = 0; z < 2; z++) v += part[(size_t)z*TOK*Dd + idx];
    x[idx] = v;
    red[d] = v*v;
    __syncthreads();
    for (int s = 256; s > 0; s >>= 1) {
        if (d < s) red[d] += red[d+s];
        __syncthreads();
    }
    float scale = rsqrtf(red[0] * (1.0f/Dd) + 1e-6f);
    float o = v * scale * w[(size_t)cur[t / Ss] * Dd + d];
    out[idx] = __uint_as_float(f2tf32(o));
}

// ---------------- reduce: x += sum of S partials ----------------
__global__ void red_add(float* __restrict__ x, const float* __restrict__ part, int S) {
    int i = blockIdx.x*256 + threadIdx.x;
    float s = x[i];
    for (int j = 0; j < S; j++) s += part[(size_t)j*TOK*Dd + i];
    x[i] = s;
}

// ---------------- flash attention (R13-exact), tf32-rounded O ----------------
#define ATT_SMEM ((32*68 + 64*68 + 64*68 + 32*68) * (int)sizeof(float))
__global__ void __launch_bounds__(256,2) fattn_k(
    const float* __restrict__ q, const float* __restrict__ k,
    const float* __restrict__ v, float* __restrict__ o)
{
    extern __shared__ float asm_[];
    float (*Qs)[68] = (float(*)[68])asm_;
    float (*Ks)[68] = (float(*)[68])(asm_ + 32*68);
    float (*Vs)[68] = (float(*)[68])(asm_ + 32*68 + 64*68);
    float (*Ps)[68] = (float(*)[68])(asm_ + 32*68 + 2*64*68);
    int qt = blockIdx.x, h = blockIdx.y, b = blockIdx.z;
    int tid = threadIdx.x;
    int row = tid >> 3;
    int sub = tid & 7;
    int base_bh = b*Ss*Dd + h*HD;
    int gq = qt*32 + row;

    #pragma unroll
    for (int l = 0; l < 2; l++) {
        int idx = tid + l*256;
        int r = idx >> 4;
        int c = (idx & 15) * 4;
        *(float4*)&Qs[r][c] = *(const float4*)&q[base_bh + (qt*32 + r)*Dd + c];
    }

    float m = -1e30f, lsum = 0.f;
    float Oacc[8];
    #pragma unroll
    for (int t = 0; t < 8; t++) Oacc[t] = 0.f;

    int nkt = qt/2 + 1;
    for (int kt = 0; kt < nkt; kt++) {
        __syncthreads();
        #pragma unroll
        for (int l = 0; l < 4; l++) {
            int idx = tid + l*256;
            int r = idx >> 4;
            int c = (idx & 15) * 4;
            *(float4*)&Ks[r][c] = *(const float4*)&k[base_bh + (kt*64 + r)*Dd + c];
            *(float4*)&Vs[r][c] = *(const float4*)&v[base_bh + (kt*64 + r)*Dd + c];
        }
        __syncthreads();

        float s[8];
        #pragma unroll
        for (int jj = 0; jj < 8; jj++) s[jj] = 0.f;
        for (int d = 0; d < HD; d++) {
            float qd = Qs[row][d];
            #pragma unroll
            for (int jj = 0; jj < 8; jj++)
                s[jj] = fmaf(qd, Ks[sub + jj*8][d], s[jj]);
        }
        int kbase = kt*64;
        float mt_ = -1e30f;
        #pragma unroll
        for (int jj = 0; jj < 8; jj++) {
            int jg = kbase + sub + jj*8;
            s[jj] = (jg <= gq) ? s[jj]*0.125f : -1e30f;
            mt_ = fmaxf(mt_, s[jj]);
        }
        mt_ = fmaxf(mt_, __shfl_xor_sync(0xffffffffu, mt_, 1));
        mt_ = fmaxf(mt_, __shfl_xor_sync(0xffffffffu, mt_, 2));
        mt_ = fmaxf(mt_, __shfl_xor_sync(0xffffffffu, mt_, 4));
        float m_new = fmaxf(m, mt_);
        float factor = expf(m - m_new);
        float lt = 0.f;
        #pragma unroll
        for (int jj = 0; jj < 8; jj++) {
            float p = expf(s[jj] - m_new);
            Ps[row][sub + jj*8] = p;
            lt += p;
        }
        lt += __shfl_xor_sync(0xffffffffu, lt, 1);
        lt += __shfl_xor_sync(0xffffffffu, lt, 2);
        lt += __shfl_xor_sync(0xffffffffu, lt, 4);
        lsum = lsum * factor + lt;
        m = m_new;
        #pragma unroll
        for (int t = 0; t < 8; t++) Oacc[t] *= factor;
        __syncwarp();

        for (int j = 0; j < 64; j++) {
            float pj = Ps[row][j];
            #pragma unroll
            for (int t = 0; t < 8; t++)
                Oacc[t] = fmaf(pj, Vs[j][sub + 8*t], Oacc[t]);
        }
    }

    float inv = 1.f / lsum;
    #pragma unroll
    for (int t = 0; t < 8; t++) {
        float vo = Oacc[t] * inv;
        o[base_bh + (size_t)gq*Dd + sub + 8*t] = __uint_as_float(f2tf32(vo));
    }
}

// ---------------- parallel pooling ----------------
__global__ void pool_k(const float* __restrict__ x, float* __restrict__ pooled) {
    int b = blockIdx.y;
    int d = blockIdx.x*128 + threadIdx.x;
    float s = 0.f;
    #pragma unroll 4
    for (int ss = 0; ss < Ss; ss++) s += x[(size_t)(b*Ss+ss)*Dd + d];
    pooled[b*Dd + d] = s * (1.f/Ss);
}

// ---------------- gating + routing (single block, reads pooled) ----------------
__global__ void gate_k(const float* __restrict__ pooled, const float* __restrict__ gw) {
    __shared__ float red[512];
    __shared__ float sc[2*(Cc+1)];
    int tid = threadIdx.x;
    for (int idx = 0; idx < 2*(Cc+1); idx++) {
        int b = idx / (Cc+1), c = idx % (Cc+1);
        red[tid] = pooled[b*Dd + tid] * gw[tid*(Cc+1) + c];
        __syncthreads();
        for (int s = 256; s > 0; s >>= 1) {
            if (tid < s) red[tid] += red[tid+s];
            __syncthreads();
        }
        if (tid == 0) sc[idx] = red[0];
        __syncthreads();
    }
    if (tid == 0) {
        float p[Bb][Cc+1];
        for (int b = 0; b < Bb; b++) {
            float mx = -1e30f;
            for (int c = 0; c < Cc+1; c++) mx = fmaxf(mx, sc[b*(Cc+1)+c]);
            float sum = 0.f;
            for (int c = 0; c < Cc+1; c++) { p[b][c] = expf(sc[b*(Cc+1)+c] - mx); sum += p[b][c]; }
            for (int c = 0; c < Cc+1; c++) p[b][c] /= sum;
        }
        float lb = 0.f;
        for (int c = 0; c < Cc+1; c++) {
            g_accp[c] += p[0][c] + p[1][c];
            float avg = 0.5f * (p[0][c] + p[1][c]);
            lb += avg*avg;
        }
        g_acclb += (float)(Cc+1) * lb;
        for (int b = 0; b < Bb; b++) {
            int co = g_cur[b];
            int j1 = (co+1) & 3, j2 = (co+2) & 3;
            float s1 = sc[b*(Cc+1)+j1], s2 = sc[b*(Cc+1)+j2];
            int w;
            if (s1 > s2) w = j1;
            else if (s2 > s1) w = j2;
            else w = (j1 < j2) ? j1 : j2;
            g_cur[b] = w;
        }
    }
}

// ---------------- host orchestration ----------------
extern "C" void kernel_launch(void* const* d_in, const int* in_sizes, int n_in,
                              void* d_out, int out_size) {
    const int*   ids   = (const int*)  d_in[0];
    const int*   start = (const int*)  d_in[1];
    const float* emb   = (const float*)d_in[2];
    const float* Wq    = (const float*)d_in[3];
    const float* Wk    = (const float*)d_in[4];
    const float* Wv    = (const float*)d_in[5];
    const float* Wo    = (const float*)d_in[6];
    const float* W1    = (const float*)d_in[7];
    const float* W2    = (const float*)d_in[8];
    const float* n1    = (const float*)d_in[9];
    const float* n2    = (const float*)d_in[10];
    const float* gw    = (const float*)d_in[11];
    const float* fnw   = (const float*)d_in[12];
    const float* fcw   = (const float*)d_in[13];
    float* out = (float*)d_out;

    float *x, *xn, *q, *k, *v, *o, *ff, *part, *pool;
    int* cur;
    cudaGetSymbolAddress((void**)&x,   g_x);
    cudaGetSymbolAddress((void**)&xn,  g_xn);
    cudaGetSymbolAddress((void**)&q,   g_q);
    cudaGetSymbolAddress((void**)&k,   g_k);
    cudaGetSymbolAddress((void**)&v,   g_v);
    cudaGetSymbolAddress((void**)&o,   g_o);
    cudaGetSymbolAddress((void**)&ff,  g_ff);
    cudaGetSymbolAddress((void**)&part, g_part);
    cudaGetSymbolAddress((void**)&pool, g_pool);
    cudaGetSymbolAddress((void**)&cur, g_cur);

    static int smem_set = 0;
    if (!smem_set) {
        cudaFuncSetAttribute(gemm_tc,    cudaFuncAttributeMaxDynamicSharedMemorySize, TC_SMEM);
        cudaFuncSetAttribute(fattn_k,    cudaFuncAttributeMaxDynamicSharedMemorySize, ATT_SMEM);
        cudaFuncSetAttribute(qkv_sk,     cudaFuncAttributeMaxDynamicSharedMemorySize, TC64_SMEM);
        cudaFuncSetAttribute(gemm_sk,    cudaFuncAttributeMaxDynamicSharedMemorySize, TC64_SMEM);
        cudaFuncSetAttribute(gemm_mid_tc,cudaFuncAttributeMaxDynamicSharedMemorySize, TC64_SMEM);
        smem_set = 1;
    }

    embednorm_k<<<TOK, Dd>>>(ids, start, emb, n1, x, xn);

    int nred = TOK*Dd/256;            // 1024 blocks
    dim3 gqkv(Dd/64, TOK/64, 6);      // 384 blocks (split-K=2 x q,k,v)
    dim3 gwo (Dd/64, TOK/64, 2);      // 128 blocks (split-K=2)
    dim3 gw1 (Ff/64, TOK/64);         // 256 blocks
    dim3 gw2 (Dd/64, TOK/64, 4);      // 256 blocks (split-K=4)
    dim3 gatt(Ss/32, Hh, Bb);         // 128 blocks
    for (int step = 0; step < 2; step++) {
        if (step > 0)
            rmsnorm_k<<<TOK, Dd>>>(x, n1, cur, xn);
        qkv_sk<<<gqkv, 256, TC64_SMEM>>>(xn, Wq, Wk, Wv, part, cur);
        qkvrope_k<<<TOK, 256>>>(part, q, k, v);
        fattn_k<<<gatt, 256, ATT_SMEM>>>(q, k, v, o);
        gemm_sk<<<gwo, 256, TC64_SMEM>>>(o, Dd, Wo, part, cur, Dd, 256);
        rednorm_k<<<TOK, Dd>>>(x, part, n2, cur, xn);
        gemm_mid_tc<<<gw1, 256, TC64_SMEM>>>(xn, W1, nullptr, ff, cur, Dd, Ff, 2);
        gemm_sk<<<gw2, 256, TC64_SMEM>>>(ff, Ff, W2, part, cur, Ff, 512);
        red_add<<<nred, 256>>>(x, part, 4);
        pool_k<<<dim3(Dd/128, Bb), 128>>>(x, pool);
        gate_k<<<1, 512>>>(pool, gw);
    }
    rmsnorm_k<<<TOK, Dd>>>(x, fnw, nullptr, xn);
    gemm_tc<<<dim3(TOK/128, Vv/128), 256, TC_SMEM>>>(xn, fcw, out, Dd, Vv, out_size);
}